// round 14
// baseline (speedup 1.0000x reference)
#include <cuda_runtime.h>
#include <math.h>

#define NQ 10
#define NL 4
#define NT 128

typedef unsigned long long u64;

// ---- packed f32x2 ops (Blackwell FFMA2 via PTX) ----
__device__ __forceinline__ u64 mul2(u64 a, u64 b) {
    u64 d; asm("mul.rn.f32x2 %0, %1, %2;" : "=l"(d) : "l"(a), "l"(b)); return d;
}
__device__ __forceinline__ u64 fma2(u64 a, u64 b, u64 c) {
    u64 d; asm("fma.rn.f32x2 %0, %1, %2, %3;" : "=l"(d) : "l"(a), "l"(b), "l"(c)); return d;
}
__device__ __forceinline__ u64 add2(u64 a, u64 b) {
    u64 d; asm("add.rn.f32x2 %0, %1, %2;" : "=l"(d) : "l"(a), "l"(b)); return d;
}
#define NEGM 0x8000000080000000ULL

// CNOT-ring bit permutation (GF(2)-linear), verified rounds 2-13.
__device__ __forceinline__ int ringperm(int v) {
    int y = v ^ (v >> 1); y ^= y >> 2; y ^= y >> 4; y ^= y >> 8;
    return (y & 0x1FF) | (((y ^ (v >> 9)) & 1) << 9);
}
// Storage slot swizzle (GF(2)-linear): XOR bits 3-5 into bits 0-2.
__device__ __forceinline__ int ssw(int i) { return i ^ ((i >> 3) & 7); }

// Packed SU(2) gate on local bit K of re[8]/im[8] (4 butterflies).
#define GATEP8(Lr, Q, K) do {                                                  \
    const float* _up = &Usm[Lr][Q][0];                                         \
    const u64 A  = *(const u64*)(_up + 0),  Bc = *(const u64*)(_up + 2);       \
    const u64 C  = *(const u64*)(_up + 4),  D  = *(const u64*)(_up + 6);       \
    const u64 nB = *(const u64*)(_up + 8),  nC = *(const u64*)(_up + 10);      \
    const u64 nD = *(const u64*)(_up + 12);                                    \
    _Pragma("unroll")                                                          \
    for (int _m = 0; _m < 8; ++_m) if (!(_m & (1 << (K)))) {                   \
        const int _n = _m | (1 << (K));                                        \
        const u64 pre = re[_m], pim = im[_m], qre = re[_n], qim = im[_n];      \
        u64 ar = mul2(A, pre);  ar = fma2(nB, pim, ar);                        \
        ar = fma2(C, qre, ar);  ar = fma2(nD, qim, ar);                        \
        u64 ai = mul2(A, pim);  ai = fma2(Bc, pre, ai);                        \
        ai = fma2(C, qim, ai);  ai = fma2(D, qre, ai);                         \
        u64 br = mul2(nC, pre); br = fma2(nD, pim, br);                        \
        br = fma2(A, qre, br);  br = fma2(Bc, qim, br);                        \
        u64 bi = mul2(nC, pim); bi = fma2(D, pre, bi);                         \
        bi = fma2(A, qim, bi);  bi = fma2(nB, qre, bi);                        \
        re[_m] = ar; im[_m] = ai; re[_n] = br; im[_n] = bi;                    \
    }                                                                          \
} while (0)

__global__ __launch_bounds__(NT, 4) void qsim_kernel(
    const float* __restrict__ inputs,   // [B, 10]
    const float* __restrict__ weights,  // [4, 10, 3]
    float* __restrict__ out)            // [B, 10]
{
    __shared__ ulonglong2 sv[1024];                 // packed (re01, im01); 16 KB
    __shared__ __align__(16) float Usm[NL][NQ][14]; // A,B,C,D,-B,-C,-D halves
    __shared__ u64 zps[4][NQ];

    const int blk = blockIdx.x;            // batches 2*blk, 2*blk+1
    const int t = threadIdx.x;

    // init |0...0> (thread t owns slots (t<<3)|0..7; ssw(0)==0)
    #pragma unroll
    for (int m = 0; m < 8; ++m) sv[(t << 3) | m] = make_ulonglong2(0ULL, 0ULL);
    if (t == 0) sv[0] = make_ulonglong2(0x3F8000003F800000ULL, 0ULL);

    // ---- phase 1: fused SU(2) row per (layer, qubit, batch-half) ----
    for (int e = t; e < NL * NQ * 2; e += NT) {
        const int half = e & 1;
        const int lq = e >> 1;
        const int l = lq / NQ, q = lq % NQ;
        const int b = 2 * blk + half;
        float x = inputs[b * NQ + q];
        x = fminf(fmaxf(x, -3.14159265358979323846f), 3.14159265358979323846f);
        float sx, cx; sincosf(0.5f * x, &sx, &cx);
        const float* w = weights + (l * NQ + q) * 3;
        float sa, ca; sincosf(0.5f * w[0], &sa, &ca);
        float sb, cb; sincosf(0.5f * w[1], &sb, &cb);
        float sc, cc; sincosf(0.5f * w[2], &sc, &cc);
        const float m00x =  ca * cx, m00y = -sa * sx;
        const float m01x = -ca * sx, m01y = -sa * cx;
        const float n00x = cb * m00x + sb * m01x, n00y = cb * m00y - sb * m01y;
        const float n01x = cb * m01x - sb * m00x, n01y = cb * m01y + sb * m00y;
        const float A = cc * n00x + sc * n00y, Bv = cc * n00y - sc * n00x;
        const float C = cc * n01x + sc * n01y, Dv = cc * n01y - sc * n01x;
        float* up = &Usm[l][q][0];
        up[0 + half] = A;   up[2 + half] = Bv;
        up[4 + half] = C;   up[6 + half] = Dv;
        up[8 + half] = -Bv; up[10 + half] = -C; up[12 + half] = -Dv;
    }
    __syncthreads();

    // round-C lane part: i = (t4<<9)|(t6<<5)|(t5<<4)|(t&15); bit 9 on lane bit 4
    const int laneC = (((t >> 4) & 1) << 9) | (((t >> 6) & 1) << 5)
                    | (((t >> 5) & 1) << 4) | (t & 15);
    const int laneCS = ssw(laneC);
    const int wbase  = ssw(ringperm(laneC));     // perm-scatter lane part
    const bool hi = (t >> 4) & 1;                // row select for bit-9 gate

    #pragma unroll 1
    for (int l = 0; l < NL; ++l) {
        u64 re[8], im[8];
        // ---- round A: bits 0-2 local (q9,q8,q7); lane-private slots ----
        {
            const int base = t << 3, sh = t & 7;
            #pragma unroll
            for (int j = 0; j < 8; ++j) {
                const ulonglong2 v = sv[base | (j ^ sh)];
                re[j] = v.x; im[j] = v.y;
            }
            GATEP8(l, 9, 0); GATEP8(l, 8, 1); GATEP8(l, 7, 2);
            #pragma unroll
            for (int j = 0; j < 8; ++j)
                sv[base | (j ^ sh)] = make_ulonglong2(re[j], im[j]);
            __syncthreads();
        }
        // ---- round B: bits 3-5 local (q6,q5,q4) ----
        {
            const int hb = (t >> 3) << 6, lb = t & 7;
            #pragma unroll
            for (int j = 0; j < 8; ++j) {
                const ulonglong2 v = sv[hb | (j << 3) | (lb ^ j)];
                re[j] = v.x; im[j] = v.y;
            }
            GATEP8(l, 6, 0); GATEP8(l, 5, 1); GATEP8(l, 4, 2);
            #pragma unroll
            for (int j = 0; j < 8; ++j)
                sv[hb | (j << 3) | (lb ^ j)] = make_ulonglong2(re[j], im[j]);
            __syncthreads();
        }
        // ---- round C: bits 6-8 local (q3,q2,q1); bit 9 via shuffle (q0) ----
        #pragma unroll
        for (int j = 0; j < 8; ++j) {
            const ulonglong2 v = sv[laneCS ^ (j << 6)];
            re[j] = v.x; im[j] = v.y;
        }
        __syncthreads();               // all reads done before any scatter
        GATEP8(l, 3, 0); GATEP8(l, 2, 1); GATEP8(l, 1, 2);
        // q0 gate on bit 9 = lane bit 4: partner lane t^16 (in-warp)
        {
            const float* up = &Usm[l][0][0];
            const u64 A  = *(const u64*)(up + 0),  Bc = *(const u64*)(up + 2);
            const u64 C  = *(const u64*)(up + 4),  D  = *(const u64*)(up + 6);
            const u64 nB = *(const u64*)(up + 8),  nC = *(const u64*)(up + 10);
            const u64 nD = *(const u64*)(up + 12);
            // row0: (u00,u01)=(A+iB, C+iD); row1: (-conj(u01), conj(u00))
            const u64 w1r  = hi ? nC : A,  w1i  = hi ? D  : Bc, nw1i = hi ? nD : nB;
            const u64 w2r  = hi ? A  : C,  w2i  = hi ? nB : D,  nw2i = hi ? Bc : nD;
            #pragma unroll
            for (int j = 0; j < 8; ++j) {
                const u64 xr = __shfl_xor_sync(0xFFFFFFFFu, re[j], 16);
                const u64 xi = __shfl_xor_sync(0xFFFFFFFFu, im[j], 16);
                const u64 p_r = hi ? xr : re[j], p_i = hi ? xi : im[j];
                const u64 q_r = hi ? re[j] : xr, q_i = hi ? im[j] : xi;
                u64 orr = mul2(w1r, p_r); orr = fma2(nw1i, p_i, orr);
                orr = fma2(w2r, q_r, orr); orr = fma2(nw2i, q_i, orr);
                u64 oii = mul2(w1r, p_i); oii = fma2(w1i, p_r, oii);
                oii = fma2(w2r, q_i, oii); oii = fma2(w2i, q_r, oii);
                re[j] = orr; im[j] = oii;
            }
        }
        if (l < 3) {
            // ring-perm scatter: slot = ssw(rp(laneC)) ^ ssw(rp(j<<6))
            #pragma unroll
            for (int j = 0; j < 8; ++j) {
                const int cj = ((j & 1) ? 0x278 : 0) ^ ((j & 2) ? 0x2F8 : 0)
                             ^ ((j & 4) ? 0x3F8 : 0);
                sv[wbase ^ cj] = make_ulonglong2(re[j], im[j]);
            }
            __syncthreads();
        } else {
            // ---- measurement from registers (ring folded into MEAS) ----
            u64 pr[8];
            #pragma unroll
            for (int j = 0; j < 8; ++j)
                pr[j] = fma2(im[j], im[j], mul2(re[j], re[j]));
            constexpr unsigned MEAS[NQ] = {0x1FF, 0x300, 0x380, 0x3C0, 0x3E0,
                                           0x3F0, 0x3F8, 0x3FC, 0x3FE, 0x3FF};
            #pragma unroll
            for (int q = 0; q < NQ; ++q) {
                const unsigned m = MEAS[q];
                u64 aP = 0, aN = 0;
                #pragma unroll
                for (int j = 0; j < 8; ++j) {
                    if (__popc((j << 6) & m) & 1) aN = add2(aN, pr[j]);
                    else                          aP = add2(aP, pr[j]);
                }
                u64 d = add2(aP, aN ^ NEGM);
                if (__popc(laneC & m) & 1) d ^= NEGM;
                d = add2(d, __shfl_xor_sync(0xFFFFFFFFu, d, 16));
                d = add2(d, __shfl_xor_sync(0xFFFFFFFFu, d, 8));
                d = add2(d, __shfl_xor_sync(0xFFFFFFFFu, d, 4));
                d = add2(d, __shfl_xor_sync(0xFFFFFFFFu, d, 2));
                d = add2(d, __shfl_xor_sync(0xFFFFFFFFu, d, 1));
                if ((t & 31) == 0) zps[t >> 5][q] = d;
            }
        }
    }
    __syncthreads();

    if (t < NQ) {
        const u64 d = add2(add2(zps[0][t], zps[1][t]),
                           add2(zps[2][t], zps[3][t]));
        out[(2 * blk)     * NQ + t] = __uint_as_float((unsigned)(d & 0xFFFFFFFFu));
        out[(2 * blk + 1) * NQ + t] = __uint_as_float((unsigned)(d >> 32));
    }
}

extern "C" void kernel_launch(void* const* d_in, const int* in_sizes, int n_in,
                              void* d_out, int out_size) {
    const float* inputs  = (const float*)d_in[0];
    const float* weights = (const float*)d_in[1];
    float* out = (float*)d_out;
    const int B = in_sizes[0] / NQ;
    qsim_kernel<<<B / 2, NT>>>(inputs, weights, out);
}

// round 15
// speedup vs baseline: 1.0317x; 1.0317x over previous
#include <cuda_runtime.h>
#include <math.h>

#define NQ 10
#define NL 4
#define NT 64

typedef unsigned long long u64;

// ---- packed f32x2 ops (Blackwell FFMA2 via PTX) ----
__device__ __forceinline__ u64 mul2(u64 a, u64 b) {
    u64 d; asm("mul.rn.f32x2 %0, %1, %2;" : "=l"(d) : "l"(a), "l"(b)); return d;
}
__device__ __forceinline__ u64 fma2(u64 a, u64 b, u64 c) {
    u64 d; asm("fma.rn.f32x2 %0, %1, %2, %3;" : "=l"(d) : "l"(a), "l"(b), "l"(c)); return d;
}
__device__ __forceinline__ u64 add2(u64 a, u64 b) {
    u64 d; asm("add.rn.f32x2 %0, %1, %2;" : "=l"(d) : "l"(a), "l"(b)); return d;
}
#define NEGM 0x8000000080000000ULL

// CNOT-ring bit permutation (GF(2)-linear), verified rounds 2-14.
__device__ __forceinline__ int ringperm(int v) {
    int y = v ^ (v >> 1); y ^= y >> 2; y ^= y >> 4; y ^= y >> 8;
    return (y & 0x1FF) | (((y ^ (v >> 9)) & 1) << 9);
}
// Storage swizzle (R10/R13-verified): XOR bits 4-7 into low nibble.
__device__ __forceinline__ int swz(int i) { return i ^ ((i >> 4) & 15); }

// Packed SU(2) gate on local bit K of re[16]/im[16] (8 butterflies).
// u00 = A+iB, u01 = C+iD; row1 = (-conj(u01), conj(u00)). Coeffs packed (b0,b1).
#define GATEP16(Lr, Q, K) do {                                                 \
    const float* _up = &Usm[Lr][Q][0];                                         \
    const u64 A  = *(const u64*)(_up + 0),  Bc = *(const u64*)(_up + 2);       \
    const u64 C  = *(const u64*)(_up + 4),  D  = *(const u64*)(_up + 6);       \
    const u64 nB = *(const u64*)(_up + 8),  nC = *(const u64*)(_up + 10);      \
    const u64 nD = *(const u64*)(_up + 12);                                    \
    _Pragma("unroll")                                                          \
    for (int _m = 0; _m < 16; ++_m) if (!(_m & (1 << (K)))) {                  \
        const int _n = _m | (1 << (K));                                        \
        const u64 pre = re[_m], pim = im[_m], qre = re[_n], qim = im[_n];      \
        u64 ar = mul2(A, pre);  ar = fma2(nB, pim, ar);                        \
        ar = fma2(C, qre, ar);  ar = fma2(nD, qim, ar);                        \
        u64 ai = mul2(A, pim);  ai = fma2(Bc, pre, ai);                        \
        ai = fma2(C, qim, ai);  ai = fma2(D, qre, ai);                         \
        u64 br = mul2(nC, pre); br = fma2(nD, pim, br);                        \
        br = fma2(A, qre, br);  br = fma2(Bc, qim, br);                        \
        u64 bi = mul2(nC, pim); bi = fma2(D, pre, bi);                         \
        bi = fma2(A, qim, bi);  bi = fma2(nB, qre, bi);                        \
        re[_m] = ar; im[_m] = ai; re[_n] = br; im[_n] = bi;                    \
    }                                                                          \
} while (0)

__global__ __launch_bounds__(NT, 7) void qsim_kernel(
    const float* __restrict__ inputs,   // [B, 10]
    const float* __restrict__ weights,  // [4, 10, 3]
    float* __restrict__ out)            // [B, 10]
{
    __shared__ ulonglong2 sv[1024];        // slot = packed (re01, im01); 16 KB
    __shared__ float Usm[NL][NQ][14];      // A,B,C,D,-B,-C,-D packed halves
    __shared__ u64 zps[2][NQ];             // per-warp partial <Z_q>

    const int blk = blockIdx.x;            // batches 2*blk, 2*blk+1
    const int t = threadIdx.x;

    // init |0...0> for both packed batches (swz(0)==0; lane-private region)
    #pragma unroll
    for (int m = 0; m < 16; ++m) sv[(t << 4) | m] = make_ulonglong2(0ULL, 0ULL);
    if (t == 0) sv[0] = make_ulonglong2(0x3F8000003F800000ULL, 0ULL);

    // ---- phase 1: fused SU(2) row per (layer, qubit, batch-half) ----
    for (int e = t; e < NL * NQ * 2; e += NT) {
        const int half = e & 1;
        const int lq = e >> 1;
        const int l = lq / NQ, q = lq % NQ;
        const int b = 2 * blk + half;
        float x = inputs[b * NQ + q];
        x = fminf(fmaxf(x, -3.14159265358979323846f), 3.14159265358979323846f);
        float sx, cx; sincosf(0.5f * x, &sx, &cx);
        const float* w = weights + (l * NQ + q) * 3;
        float sa, ca; sincosf(0.5f * w[0], &sa, &ca);
        float sb, cb; sincosf(0.5f * w[1], &sb, &cb);
        float sc, cc; sincosf(0.5f * w[2], &sc, &cc);
        const float m00x =  ca * cx, m00y = -sa * sx;
        const float m01x = -ca * sx, m01y = -sa * cx;
        const float n00x = cb * m00x + sb * m01x, n00y = cb * m00y - sb * m01y;
        const float n01x = cb * m01x - sb * m00x, n01y = cb * m01y + sb * m00y;
        const float A = cc * n00x + sc * n00y, Bv = cc * n00y - sc * n00x;
        const float C = cc * n01x + sc * n01y, Dv = cc * n01y - sc * n01x;
        float* up = &Usm[l][q][0];
        up[0 + half] = A;   up[2 + half] = Bv;
        up[4 + half] = C;   up[6 + half] = Dv;
        up[8 + half] = -Bv; up[10 + half] = -C; up[12 + half] = -Dv;
    }
    __syncthreads();

    const int wbase = swz(ringperm(t));    // perm-scatter lane part
    const int tC = t ^ (t >> 4);           // swz(t) for t < 64

    #pragma unroll 1
    for (int l = 0; l < NL; ++l) {
        u64 re[16], im[16];
        // ---- round A: bits 0-3 local (qubits 9..6); lane-private slots ----
        {
            const int base = t << 4, sh = t & 15;
            #pragma unroll
            for (int j = 0; j < 16; ++j) {
                const ulonglong2 v = sv[base | (j ^ sh)];
                re[j] = v.x; im[j] = v.y;
            }
            GATEP16(l, 9, 0); GATEP16(l, 8, 1);
            GATEP16(l, 7, 2); GATEP16(l, 6, 3);
            #pragma unroll
            for (int j = 0; j < 16; ++j)
                sv[base | (j ^ sh)] = make_ulonglong2(re[j], im[j]);
            __syncthreads();
        }
        // ---- round B: bits 4-7 local (qubits 5..2) ----
        {
            const int hb = (t >> 4) << 8, lb = t & 15;
            #pragma unroll
            for (int j = 0; j < 16; ++j) {
                const ulonglong2 v = sv[hb | (j << 4) | (lb ^ j)];
                re[j] = v.x; im[j] = v.y;
            }
            GATEP16(l, 5, 0); GATEP16(l, 4, 1);
            GATEP16(l, 3, 2); GATEP16(l, 2, 3);
            #pragma unroll
            for (int j = 0; j < 16; ++j)
                sv[hb | (j << 4) | (lb ^ j)] = make_ulonglong2(re[j], im[j]);
            __syncthreads();
        }
        // ---- round C: bits 6-9 free, gates on bits 8,9 (qubits 1,0) ----
        #pragma unroll
        for (int j = 0; j < 16; ++j) {
            const ulonglong2 v = sv[tC ^ (j << 6) ^ ((j & 3) << 2)];
            re[j] = v.x; im[j] = v.y;
        }
        __syncthreads();               // full state in registers before scatter
        GATEP16(l, 1, 2); GATEP16(l, 0, 3);
        if (l < 3) {
            // in-place ring-perm scatter: addr = swz(rp(j<<6)) ^ swz(rp(t))
            #pragma unroll
            for (int j = 0; j < 16; ++j) {
                const int rpj = ((j & 1) ? 0x27F : 0) ^ ((j & 2) ? 0x2FF : 0)
                              ^ ((j & 4) ? 0x3FF : 0) ^ ((j & 8) ? 0x1FF : 0);
                const int srpj = rpj ^ ((rpj >> 4) & 15);
                sv[wbase ^ srpj] = make_ulonglong2(re[j], im[j]);
            }
            __syncthreads();
        } else {
            // ---- measurement straight from registers (ring folded in MEAS) ----
            u64 pr[16];
            #pragma unroll
            for (int j = 0; j < 16; ++j)
                pr[j] = fma2(im[j], im[j], mul2(re[j], re[j]));
            constexpr unsigned MEAS[NQ] = {0x1FF, 0x300, 0x380, 0x3C0, 0x3E0,
                                           0x3F0, 0x3F8, 0x3FC, 0x3FE, 0x3FF};
            #pragma unroll
            for (int q = 0; q < NQ; ++q) {
                const unsigned m = MEAS[q];
                u64 aP = 0, aN = 0;
                #pragma unroll
                for (int j = 0; j < 16; ++j) {
                    if (__popc((j << 6) & m) & 1) aN = add2(aN, pr[j]);
                    else                          aP = add2(aP, pr[j]);
                }
                u64 d = add2(aP, aN ^ NEGM);
                if (__popc(t & m) & 1) d ^= NEGM;
                d = add2(d, __shfl_xor_sync(0xFFFFFFFFu, d, 16));
                d = add2(d, __shfl_xor_sync(0xFFFFFFFFu, d, 8));
                d = add2(d, __shfl_xor_sync(0xFFFFFFFFu, d, 4));
                d = add2(d, __shfl_xor_sync(0xFFFFFFFFu, d, 2));
                d = add2(d, __shfl_xor_sync(0xFFFFFFFFu, d, 1));
                if ((t & 31) == 0) zps[t >> 5][q] = d;
            }
        }
    }
    __syncthreads();

    if (t < NQ) {
        const u64 d = add2(zps[0][t], zps[1][t]);
        out[(2 * blk)     * NQ + t] = __uint_as_float((unsigned)(d & 0xFFFFFFFFu));
        out[(2 * blk + 1) * NQ + t] = __uint_as_float((unsigned)(d >> 32));
    }
}

extern "C" void kernel_launch(void* const* d_in, const int* in_sizes, int n_in,
                              void* d_out, int out_size) {
    const float* inputs  = (const float*)d_in[0];
    const float* weights = (const float*)d_in[1];
    float* out = (float*)d_out;
    const int B = in_sizes[0] / NQ;
    qsim_kernel<<<B / 2, NT>>>(inputs, weights, out);
}

// round 16
// speedup vs baseline: 1.4429x; 1.3986x over previous
#include <cuda_runtime.h>
#include <math.h>

#define NQ 10
#define NL 4
#define NT 64

typedef unsigned long long u64;

// ---- packed f32x2 ops (Blackwell FFMA2 via PTX) ----
__device__ __forceinline__ u64 mul2(u64 a, u64 b) {
    u64 d; asm("mul.rn.f32x2 %0, %1, %2;" : "=l"(d) : "l"(a), "l"(b)); return d;
}
__device__ __forceinline__ u64 fma2(u64 a, u64 b, u64 c) {
    u64 d; asm("fma.rn.f32x2 %0, %1, %2, %3;" : "=l"(d) : "l"(a), "l"(b), "l"(c)); return d;
}
__device__ __forceinline__ u64 add2(u64 a, u64 b) {
    u64 d; asm("add.rn.f32x2 %0, %1, %2;" : "=l"(d) : "l"(a), "l"(b)); return d;
}
#define NEGM 0x8000000080000000ULL

// packed complex multiply-in-place: (xr+ixi) *= (br+ibi)
__device__ __forceinline__ void cmul2(u64& xr, u64& xi, u64 br, u64 bi) {
    const u64 nr = fma2(xi ^ NEGM, bi, mul2(xr, br));
    const u64 ni = fma2(xi, br, mul2(xr, bi));
    xr = nr; xi = ni;
}

// CNOT-ring bit permutation (GF(2)-linear), verified rounds 2-15.
__device__ __forceinline__ int ringperm(int v) {
    int y = v ^ (v >> 1); y ^= y >> 2; y ^= y >> 4; y ^= y >> 8;
    return (y & 0x1FF) | (((y ^ (v >> 9)) & 1) << 9);
}
// Storage swizzle (R10/R13-verified): XOR bits 4-7 into low nibble.
__device__ __forceinline__ int swz(int i) { return i ^ ((i >> 4) & 15); }

// Packed SU(2) gate on local bit K of re[16]/im[16] (8 butterflies).
// u00 = A+iB, u01 = C+iD; row1 = (-conj(u01), conj(u00)). Coeffs packed (b0,b1).
#define GATEP16(Lr, Q, K) do {                                                 \
    const float* _up = &Usm[Lr][Q][0];                                         \
    const u64 A  = *(const u64*)(_up + 0),  Bc = *(const u64*)(_up + 2);       \
    const u64 C  = *(const u64*)(_up + 4),  D  = *(const u64*)(_up + 6);       \
    const u64 nB = *(const u64*)(_up + 8),  nC = *(const u64*)(_up + 10);      \
    const u64 nD = *(const u64*)(_up + 12);                                    \
    _Pragma("unroll")                                                          \
    for (int _m = 0; _m < 16; ++_m) if (!(_m & (1 << (K)))) {                  \
        const int _n = _m | (1 << (K));                                        \
        const u64 pre = re[_m], pim = im[_m], qre = re[_n], qim = im[_n];      \
        u64 ar = mul2(A, pre);  ar = fma2(nB, pim, ar);                        \
        ar = fma2(C, qre, ar);  ar = fma2(nD, qim, ar);                        \
        u64 ai = mul2(A, pim);  ai = fma2(Bc, pre, ai);                        \
        ai = fma2(C, qim, ai);  ai = fma2(D, qre, ai);                         \
        u64 br = mul2(nC, pre); br = fma2(nD, pim, br);                        \
        br = fma2(A, qre, br);  br = fma2(Bc, qim, br);                        \
        u64 bi = mul2(nC, pim); bi = fma2(D, pre, bi);                         \
        bi = fma2(A, qim, bi);  bi = fma2(nB, qre, bi);                        \
        re[_m] = ar; im[_m] = ai; re[_n] = br; im[_n] = bi;                    \
    }                                                                          \
} while (0)

__global__ __launch_bounds__(NT, 6) void qsim_kernel(
    const float* __restrict__ inputs,   // [B, 10]
    const float* __restrict__ weights,  // [4, 10, 3]
    float* __restrict__ out)            // [B, 10]
{
    __shared__ ulonglong2 sv[1024];        // slot = packed (re01, im01); 16 KB
    __shared__ float Usm[NL][NQ][14];      // A,B,C,D,-B,-C,-D packed halves
    __shared__ u64 zps[2][NQ];             // per-warp partial <Z_q>

    const int blk = blockIdx.x;            // batches 2*blk, 2*blk+1
    const int t = threadIdx.x;

    // ---- phase 1: fused SU(2) row per (layer, qubit, batch-half) ----
    for (int e = t; e < NL * NQ * 2; e += NT) {
        const int half = e & 1;
        const int lq = e >> 1;
        const int l = lq / NQ, q = lq % NQ;
        const int b = 2 * blk + half;
        float x = inputs[b * NQ + q];
        x = fminf(fmaxf(x, -3.14159265358979323846f), 3.14159265358979323846f);
        float sx, cx; sincosf(0.5f * x, &sx, &cx);
        const float* w = weights + (l * NQ + q) * 3;
        float sa, ca; sincosf(0.5f * w[0], &sa, &ca);
        float sb, cb; sincosf(0.5f * w[1], &sb, &cb);
        float sc, cc; sincosf(0.5f * w[2], &sc, &cc);
        const float m00x =  ca * cx, m00y = -sa * sx;
        const float m01x = -ca * sx, m01y = -sa * cx;
        const float n00x = cb * m00x + sb * m01x, n00y = cb * m00y - sb * m01y;
        const float n01x = cb * m01x - sb * m00x, n01y = cb * m01y + sb * m00y;
        const float A = cc * n00x + sc * n00y, Bv = cc * n00y - sc * n00x;
        const float C = cc * n01x + sc * n01y, Dv = cc * n01y - sc * n01x;
        float* up = &Usm[l][q][0];
        up[0 + half] = A;   up[2 + half] = Bv;
        up[4 + half] = C;   up[6 + half] = Dv;
        up[8 + half] = -Bv; up[10 + half] = -C; up[12 + half] = -Dv;
    }
    __syncthreads();

    const int wbase = swz(ringperm(t));    // perm-scatter lane part
    const int tC = t ^ (t >> 4);           // swz(t) for t < 64

    // column-0 factor of qubit q: bit 0 -> u00 = (A, B); bit 1 -> u10 = (-C, D)
    #define FFAC(Q, BIT, FR, FI) do {                                          \
        const float* _u = &Usm[0][Q][0];                                       \
        FR = *(const u64*)(_u + ((BIT) ? 10 : 0));                             \
        FI = *(const u64*)(_u + ((BIT) ? 6 : 2));                              \
    } while (0)

    // ---- layer 0: product state amp(i) = prod_p U_{9-p}[bit_p(i)][0] ----
    {
        // P_low over lane bits 0-5 (qubits 9..4)
        u64 plr, pli;
        FFAC(9, t & 1, plr, pli);
        #pragma unroll
        for (int p = 1; p < 6; ++p) {
            u64 fr, fi; FFAC(9 - p, (t >> p) & 1, fr, fi);
            cmul2(plr, pli, fr, fi);
        }
        // H2[a] = F_q3(a0) * F_q2(a1)   (i bits 6,7)
        u64 h2r[4], h2i[4];
        #pragma unroll
        for (int a = 0; a < 4; ++a) {
            FFAC(3, a & 1, h2r[a], h2i[a]);
            u64 fr, fi; FFAC(2, (a >> 1) & 1, fr, fi);
            cmul2(h2r[a], h2i[a], fr, fi);
        }
        // K2[m] = F_q1(m0) * F_q0(m1) * P_low   (i bits 8,9)
        u64 k2r[4], k2i[4];
        #pragma unroll
        for (int m = 0; m < 4; ++m) {
            FFAC(1, m & 1, k2r[m], k2i[m]);
            u64 fr, fi; FFAC(0, (m >> 1) & 1, fr, fi);
            cmul2(k2r[m], k2i[m], fr, fi);
            cmul2(k2r[m], k2i[m], plr, pli);
        }
        // amps in round-C layout (i = (j<<6)|t) + ring-perm scatter
        #pragma unroll
        for (int j = 0; j < 16; ++j) {
            u64 rr = h2r[j & 3], ri = h2i[j & 3];
            cmul2(rr, ri, k2r[j >> 2], k2i[j >> 2]);
            const int rpj = ((j & 1) ? 0x27F : 0) ^ ((j & 2) ? 0x2FF : 0)
                          ^ ((j & 4) ? 0x3FF : 0) ^ ((j & 8) ? 0x1FF : 0);
            const int srpj = rpj ^ ((rpj >> 4) & 15);
            sv[wbase ^ srpj] = make_ulonglong2(rr, ri);
        }
        __syncthreads();
    }

    // ---- layers 1-3: rounds A, B, C (scatter for l<3, measure at l==3) ----
    #pragma unroll 1
    for (int l = 1; l < NL; ++l) {
        u64 re[16], im[16];
        // ---- round A: bits 0-3 local (qubits 9..6); lane-private slots ----
        {
            const int base = t << 4, sh = t & 15;
            #pragma unroll
            for (int j = 0; j < 16; ++j) {
                const ulonglong2 v = sv[base | (j ^ sh)];
                re[j] = v.x; im[j] = v.y;
            }
            GATEP16(l, 9, 0); GATEP16(l, 8, 1);
            GATEP16(l, 7, 2); GATEP16(l, 6, 3);
            #pragma unroll
            for (int j = 0; j < 16; ++j)
                sv[base | (j ^ sh)] = make_ulonglong2(re[j], im[j]);
            __syncthreads();
        }
        // ---- round B: bits 4-7 local (qubits 5..2) ----
        {
            const int hb = (t >> 4) << 8, lb = t & 15;
            #pragma unroll
            for (int j = 0; j < 16; ++j) {
                const ulonglong2 v = sv[hb | (j << 4) | (lb ^ j)];
                re[j] = v.x; im[j] = v.y;
            }
            GATEP16(l, 5, 0); GATEP16(l, 4, 1);
            GATEP16(l, 3, 2); GATEP16(l, 2, 3);
            #pragma unroll
            for (int j = 0; j < 16; ++j)
                sv[hb | (j << 4) | (lb ^ j)] = make_ulonglong2(re[j], im[j]);
            __syncthreads();
        }
        // ---- round C: bits 6-9 free, gates on bits 8,9 (qubits 1,0) ----
        #pragma unroll
        for (int j = 0; j < 16; ++j) {
            const ulonglong2 v = sv[tC ^ (j << 6) ^ ((j & 3) << 2)];
            re[j] = v.x; im[j] = v.y;
        }
        __syncthreads();               // full state in registers before scatter
        GATEP16(l, 1, 2); GATEP16(l, 0, 3);
        if (l < 3) {
            // in-place ring-perm scatter: addr = swz(rp(j<<6)) ^ swz(rp(t))
            #pragma unroll
            for (int j = 0; j < 16; ++j) {
                const int rpj = ((j & 1) ? 0x27F : 0) ^ ((j & 2) ? 0x2FF : 0)
                              ^ ((j & 4) ? 0x3FF : 0) ^ ((j & 8) ? 0x1FF : 0);
                const int srpj = rpj ^ ((rpj >> 4) & 15);
                sv[wbase ^ srpj] = make_ulonglong2(re[j], im[j]);
            }
            __syncthreads();
        } else {
            // ---- measurement straight from registers (ring folded in MEAS) ----
            u64 pr[16];
            #pragma unroll
            for (int j = 0; j < 16; ++j)
                pr[j] = fma2(im[j], im[j], mul2(re[j], re[j]));
            constexpr unsigned MEAS[NQ] = {0x1FF, 0x300, 0x380, 0x3C0, 0x3E0,
                                           0x3F0, 0x3F8, 0x3FC, 0x3FE, 0x3FF};
            #pragma unroll
            for (int q = 0; q < NQ; ++q) {
                const unsigned m = MEAS[q];
                u64 aP = 0, aN = 0;
                #pragma unroll
                for (int j = 0; j < 16; ++j) {
                    if (__popc((j << 6) & m) & 1) aN = add2(aN, pr[j]);
                    else                          aP = add2(aP, pr[j]);
                }
                u64 d = add2(aP, aN ^ NEGM);
                if (__popc(t & m) & 1) d ^= NEGM;
                d = add2(d, __shfl_xor_sync(0xFFFFFFFFu, d, 16));
                d = add2(d, __shfl_xor_sync(0xFFFFFFFFu, d, 8));
                d = add2(d, __shfl_xor_sync(0xFFFFFFFFu, d, 4));
                d = add2(d, __shfl_xor_sync(0xFFFFFFFFu, d, 2));
                d = add2(d, __shfl_xor_sync(0xFFFFFFFFu, d, 1));
                if ((t & 31) == 0) zps[t >> 5][q] = d;
            }
        }
    }
    __syncthreads();

    if (t < NQ) {
        const u64 d = add2(zps[0][t], zps[1][t]);
        out[(2 * blk)     * NQ + t] = __uint_as_float((unsigned)(d & 0xFFFFFFFFu));
        out[(2 * blk + 1) * NQ + t] = __uint_as_float((unsigned)(d >> 32));
    }
}

extern "C" void kernel_launch(void* const* d_in, const int* in_sizes, int n_in,
                              void* d_out, int out_size) {
    const float* inputs  = (const float*)d_in[0];
    const float* weights = (const float*)d_in[1];
    float* out = (float*)d_out;
    const int B = in_sizes[0] / NQ;
    qsim_kernel<<<B / 2, NT>>>(inputs, weights, out);
}